// round 16
// baseline (speedup 1.0000x reference)
#include <cuda_runtime.h>
#include <cuda_fp16.h>
#include <math.h>

typedef unsigned int u32;

#define NOSC 256
#define DDIM 64
#define NSTEPS 10

// smem byte offsets (total ~97 KB -> 2 CTAs/SM)
#define SM_XHI 0
#define SM_XLO 32768
#define SM_OHI 65536
#define SM_WB  73728          // 3 ring buffers x 8192B
#define SM_RED 98304
#define SM_TOTAL 99328

// W prepacked fp16 (hi only): 16 chunks (16 j-cols each, 8KB), warp-private regions:
// [pass(8192B)][warp(1024B)][plane(512B)][row*16B][j*2B]
__device__ __half g_Wpk[16 * 4096];
// h prepacked fp16 pairs in fragment-lane-major order: [warp][seg*2+half][lane][uint4]
__device__ uint4 g_hpk[8 * 8 * 32];

__global__ void wprep_kernel(const float* __restrict__ W) {
    int idx = blockIdx.x * 256 + threadIdx.x;   // 65536
    int i = idx >> 8, j = idx & 255;
    float v = W[i * 256 + j];
    __half hi = __float2half_rn(v);
    int p = j >> 4, plane = (j >> 3) & 1, jj = j & 7;
    int w = i >> 5, row = i & 31;
    g_Wpk[p * 4096 + w * 512 + plane * 256 + row * 8 + jj] = hi;
}

__global__ void hprep_kernel(const float* __restrict__ h) {
    int idx = blockIdx.x * 256 + threadIdx.x;   // 8192 = 256 rows x 32 col-pairs
    int i = idx >> 5, ep = idx & 31, e = ep * 2;
    float v0 = h[i * DDIM + e], v1 = h[i * DDIM + e + 1];
    __half h0 = __float2half_rn(v0), h1 = __float2half_rn(v1);
    u32 val = (u32)__half_as_ushort(h0) | ((u32)__half_as_ushort(h1) << 16);
    int w = i >> 5, mt = (i >> 4) & 1, hh = (i >> 3) & 1, g = i & 7;
    int nt = e >> 3, half = nt >> 2, slot = nt & 3, tid4 = (e >> 1) & 3;
    int lane = g * 4 + tid4, seg = mt * 2 + hh;
    ((u32*)g_hpk)[(((w * 8) + seg * 2 + half) * 32 + lane) * 4 + slot] = val;
}

// ---------------- PTX helpers (baseline sm_80-level; compile for plain sm_100) ----------------
__device__ __forceinline__ u32 smem_u32(const void* p) {
    u32 a; asm("{ .reg .u64 t; cvta.to.shared.u64 t, %1; cvt.u32.u64 %0, t; }"
               : "=r"(a) : "l"(p));
    return a;
}
__device__ __forceinline__ void ldsm_x4(u32 addr, u32* r) {
    asm volatile("ldmatrix.sync.aligned.m8n8.x4.shared.b16 {%0,%1,%2,%3}, [%4];"
                 : "=r"(r[0]), "=r"(r[1]), "=r"(r[2]), "=r"(r[3]) : "r"(addr));
}
__device__ __forceinline__ void ldsm_x4t(u32 addr, u32* r) {
    asm volatile("ldmatrix.sync.aligned.m8n8.x4.trans.shared.b16 {%0,%1,%2,%3}, [%4];"
                 : "=r"(r[0]), "=r"(r[1]), "=r"(r[2]), "=r"(r[3]) : "r"(addr));
}
__device__ __forceinline__ void mma16816(float* c, const u32* a, u32 b0, u32 b1) {
    asm volatile("mma.sync.aligned.m16n8k16.row.col.f32.f16.f16.f32 "
                 "{%0,%1,%2,%3}, {%4,%5,%6,%7}, {%8,%9}, {%0,%1,%2,%3};"
                 : "+f"(c[0]), "+f"(c[1]), "+f"(c[2]), "+f"(c[3])
                 : "r"(a[0]), "r"(a[1]), "r"(a[2]), "r"(a[3]), "r"(b0), "r"(b1));
}
#define CP_ASYNC16(dst, src) \
    asm volatile("cp.async.cg.shared.global [%0], [%1], 16;" :: "r"(dst), "l"(src) : "memory")
#define CP_COMMIT()  asm volatile("cp.async.commit_group;" ::: "memory")
#define CP_WAIT1()   asm volatile("cp.async.wait_group 1;" ::: "memory")
#define CP_WAIT0()   asm volatile("cp.async.wait_group 0;" ::: "memory")

__device__ __forceinline__ u32 pack_h2(float v0, float v1, u32& lo_out) {
    __half h0 = __float2half_rn(v0), h1 = __float2half_rn(v1);
    __half l0 = __float2half_rn(v0 - __half2float(h0));
    __half l1 = __float2half_rn(v1 - __half2float(h1));
    lo_out = (u32)__half_as_ushort(l0) | ((u32)__half_as_ushort(l1) << 16);
    return (u32)__half_as_ushort(h0) | ((u32)__half_as_ushort(h1) << 16);
}
__device__ __forceinline__ float h2f_lo(u32 v) {
    return __half2float(__ushort_as_half((unsigned short)(v & 0xffffu)));
}
__device__ __forceinline__ float h2f_hi(u32 v) {
    return __half2float(__ushort_as_half((unsigned short)(v >> 16)));
}

// XOR chunk swizzle: 128B rows, 16B granules; granule' = granule ^ (row & 7)
__device__ __forceinline__ u32 xaddr(int row, int chunk) {
    return (u32)(row * 128 + ((chunk ^ (row & 7)) << 4));
}

__global__ __launch_bounds__(256, 2)
void akorn_kernel(const float* __restrict__ x_in,
                  const float* __restrict__ eta_p,
                  const float* __restrict__ A,
                  const float* __restrict__ w_ro,
                  const float* __restrict__ b_ro,
                  float* __restrict__ out,
                  float* __restrict__ x_out,
                  int write_x)
{
    extern __shared__ char smp[];
    const int b = blockIdx.x;
    const int t = threadIdx.x;
    const int wid = t >> 5, lane = t & 31;
    const int g = lane >> 2, tid4 = lane & 3;
    const int lr = lane & 15, lh = lane >> 4;
    const int l8 = lane & 7, q8 = lane >> 3;
    const int wbase = wid * 32;
    const u32 sb = smem_u32(smp);
    const float eta = __ldg(eta_p);

    // ---- initial x: load row t, normalize, store fp16 hi/lo (swizzled) ----
    {
        const float* xrow = x_in + (size_t)b * NOSC * DDIM + t * DDIM;
        float xr[DDIM]; float ss = 0.f;
        #pragma unroll
        for (int k = 0; k < 16; k++) {
            float4 v = __ldg((const float4*)&xrow[k * 4]);
            xr[4*k] = v.x; xr[4*k+1] = v.y; xr[4*k+2] = v.z; xr[4*k+3] = v.w;
            ss += v.x*v.x + v.y*v.y + v.z*v.z + v.w*v.w;
        }
        float inv = 1.0f / fmaxf(sqrtf(ss), 1e-12f);
        #pragma unroll
        for (int c = 0; c < DDIM; c++) xr[c] *= inv;
        #pragma unroll
        for (int q = 0; q < 8; q++) {
            u32 hs[4], ls[4];
            #pragma unroll
            for (int m = 0; m < 4; m++)
                hs[m] = pack_h2(xr[q*8 + 2*m], xr[q*8 + 2*m + 1], ls[m]);
            u32 a = xaddr(t, q);
            *(uint4*)(smp + SM_XHI + a) = make_uint4(hs[0], hs[1], hs[2], hs[3]);
            *(uint4*)(smp + SM_XLO + a) = make_uint4(ls[0], ls[1], ls[2], ls[3]);
        }
    }
    // ---- Omega = A - A^T, fp16 hi only (swizzled) ----
    if (t < DDIM) {
        int f = t;
        #pragma unroll 2
        for (int q = 0; q < 8; q++) {
            u32 hs[4];
            #pragma unroll
            for (int m = 0; m < 4; m++) {
                int e0 = q*8 + 2*m, e1 = e0 + 1;
                float v0 = __ldg(&A[f * DDIM + e0]) - __ldg(&A[e0 * DDIM + f]);
                float v1 = __ldg(&A[f * DDIM + e1]) - __ldg(&A[e1 * DDIM + f]);
                __half h0 = __float2half_rn(v0), h1 = __float2half_rn(v1);
                hs[m] = (u32)__half_as_ushort(h0) | ((u32)__half_as_ushort(h1) << 16);
            }
            *(uint4*)(smp + SM_OHI + xaddr(f, q)) = make_uint4(hs[0], hs[1], hs[2], hs[3]);
        }
    }
    __syncthreads();

    // Per-warp chunk copy: warp wid copies ONLY its own 1KB region of pass p into ring buf
    auto cp_chunk = [&](int p) {
        u32 sdst = sb + SM_WB + (u32)((p % 3) * 8192 + wid * 1024 + lane * 16);
        const char* src = ((const char*)g_Wpk) + (size_t)p * 8192 + wid * 1024 + lane * 16;
        CP_ASYNC16(sdst, src);
        CP_ASYNC16(sdst + 512, src + 512);
    };

    float part = 0.f;

    for (int step = 0; step < NSTEPS; step++) {
        float C[2][8][4];
        #pragma unroll
        for (int mt = 0; mt < 2; mt++)
            #pragma unroll
            for (int nt = 0; nt < 8; nt++)
                #pragma unroll
                for (int q = 0; q < 4; q++) C[mt][nt][q] = 0.f;

        // prefetch W chunks 0,1 (warp-private dst; no hazard with X)
        cp_chunk(0); CP_COMMIT();
        cp_chunk(1); CP_COMMIT();

        // ---- Omega part BEFORE the visibility barrier: A reads only OWN rows
        // (written by this warp last step — program order), B is constant Ω. ----
        #pragma unroll
        for (int ks = 0; ks < 4; ks++) {
            const int f0 = ks * 16;
            u32 ah[2][4];
            #pragma unroll
            for (int mt = 0; mt < 2; mt++) {
                int arow = wbase + mt*16 + lr;
                ldsm_x4(sb + SM_XHI + xaddr(arow, (f0 >> 3) + lh), ah[mt]);
            }
            #pragma unroll
            for (int nt2 = 0; nt2 < 8; nt2 += 2) {
                u32 bo[4];
                ldsm_x4t(sb + SM_OHI + xaddr(f0 + ((q8 & 1) << 3) + l8, nt2 + (q8 >> 1)), bo);
                #pragma unroll
                for (int mt = 0; mt < 2; mt++) {
                    mma16816(C[mt][nt2],     ah[mt], bo[0], bo[1]);
                    mma16816(C[mt][nt2 + 1], ah[mt], bo[2], bo[3]);
                }
            }
        }

        __syncthreads();   // all warps' X hi stores visible before W passes read ALL rows

        // ---- W part: 16 warp-async passes of 16 j-cols, 3-buffer ring, depth-2 prefetch ----
        for (int p = 0; p < 16; p++) {
            if (p < 15) CP_WAIT1(); else CP_WAIT0();
            if (p < 14) { cp_chunk(p + 2); CP_COMMIT(); }
            const u32 wb = sb + SM_WB + (u32)((p % 3) * 8192 + wid * 1024);
            u32 aw[2][4];
            #pragma unroll
            for (int mt = 0; mt < 2; mt++) {
                u32 ra = (u32)(lh * 512 + (mt*16 + lr) * 16);
                ldsm_x4(wb + ra, aw[mt]);
            }
            const int jb = p * 16;
            #pragma unroll
            for (int nt2 = 0; nt2 < 8; nt2 += 2) {
                u32 bx[4];
                ldsm_x4t(sb + SM_XHI + xaddr(jb + ((q8 & 1) << 3) + l8, nt2 + (q8 >> 1)), bx);
                #pragma unroll
                for (int mt = 0; mt < 2; mt++) {
                    mma16816(C[mt][nt2],     aw[mt], bx[0], bx[1]);
                    mma16816(C[mt][nt2 + 1], aw[mt], bx[2], bx[3]);
                }
            }
        }

        // ---- h fragments (global, read-only) ----
        uint4 hreg[8];
        {
            const uint4* hp = g_hpk + (size_t)(wid * 8) * 32 + lane;
            #pragma unroll
            for (int k = 0; k < 8; k++) hreg[k] = __ldg(hp + k * 32);
        }

        // ---- epilogue COMPUTE phase (reads/writes only OWN rows; XLO is
        // owner-private so lo stores are safe pre-barrier; hi held in regs) ----
        u32 hip[4][8];
        #pragma unroll
        for (int mt = 0; mt < 2; mt++) {
            #pragma unroll
            for (int hh = 0; hh < 2; hh++) {
                const int row = wbase + mt*16 + g + hh*8;
                const int seg = mt * 2 + hh;
                float xv[16], dvv[16];
                float dot = 0.f;
                #pragma unroll
                for (int nt = 0; nt < 8; nt++) {
                    const u32* hw = (const u32*)&hreg[seg * 2 + (nt >> 2)];
                    u32 hv = hw[nt & 3];
                    float d0 = C[mt][nt][hh*2 + 0] + h2f_lo(hv);
                    float d1 = C[mt][nt][hh*2 + 1] + h2f_hi(hv);
                    u32 off = xaddr(row, nt) + (u32)(tid4 * 4);
                    u32 vh = *(const u32*)(smp + SM_XHI + off);
                    u32 vl = *(const u32*)(smp + SM_XLO + off);
                    float x0 = h2f_lo(vh) + h2f_lo(vl);
                    float x1 = h2f_hi(vh) + h2f_hi(vl);
                    dot += x0 * d0 + x1 * d1;
                    xv[nt*2] = x0; xv[nt*2+1] = x1;
                    dvv[nt*2] = d0; dvv[nt*2+1] = d1;
                }
                dot += __shfl_xor_sync(0xffffffffu, dot, 1);
                dot += __shfl_xor_sync(0xffffffffu, dot, 2);
                float ss = 0.f;
                #pragma unroll
                for (int c = 0; c < 16; c++) {
                    xv[c] = xv[c] + eta * (dvv[c] - dot * xv[c]);
                    ss += xv[c] * xv[c];
                }
                ss += __shfl_xor_sync(0xffffffffu, ss, 1);
                ss += __shfl_xor_sync(0xffffffffu, ss, 2);
                float inv = 1.0f / fmaxf(sqrtf(ss), 1e-12f);
                #pragma unroll
                for (int c = 0; c < 16; c++) xv[c] *= inv;
                #pragma unroll
                for (int nt = 0; nt < 8; nt++) {
                    u32 off = xaddr(row, nt) + (u32)(tid4 * 4);
                    u32 lo; u32 hi = pack_h2(xv[nt*2], xv[nt*2+1], lo);
                    *(u32*)(smp + SM_XLO + off) = lo;   // owner-private: safe now
                    hip[seg][nt] = hi;                  // deferred to post-barrier
                }
                if (step == NSTEPS - 1) {
                    #pragma unroll
                    for (int nt = 0; nt < 8; nt++) {
                        const int col = nt*8 + tid4*2;
                        float2 wv = *(const float2*)&w_ro[col];
                        part += xv[nt*2] * wv.x + xv[nt*2+1] * wv.y;
                    }
                    if (write_x) {
                        #pragma unroll
                        for (int nt = 0; nt < 8; nt++) {
                            const int col = nt*8 + tid4*2;
                            *(float2*)&x_out[(size_t)b * NOSC * DDIM + row * DDIM + col] =
                                make_float2(xv[nt*2], xv[nt*2+1]);
                        }
                    }
                }
            }
        }

        __syncthreads();   // all warps' X reads (W passes) done before hi writes

        // ---- STORE phase: publish new X hi ----
        #pragma unroll
        for (int seg = 0; seg < 4; seg++) {
            const int row = wbase + (seg >> 1)*16 + g + (seg & 1)*8;
            #pragma unroll
            for (int nt = 0; nt < 8; nt++)
                *(u32*)(smp + SM_XHI + xaddr(row, nt) + (u32)(tid4 * 4)) = hip[seg][nt];
        }
    }

    // ---- readout reduction ----
    float* red = (float*)(smp + SM_RED);
    red[t] = part;
    __syncthreads();
    #pragma unroll
    for (int s = 128; s > 0; s >>= 1) {
        if (t < s) red[t] += red[t + s];
        __syncthreads();
    }
    if (t == 0) out[b] = red[0] / (float)NOSC + __ldg(b_ro);
}

extern "C" void kernel_launch(void* const* d_in, const int* in_sizes, int n_in,
                              void* d_out, int out_size) {
    const float* x    = (const float*)d_in[0];
    const float* eta  = (const float*)d_in[1];
    const float* W    = (const float*)d_in[2];
    const float* A    = (const float*)d_in[3];
    const float* h    = (const float*)d_in[4];
    const float* w_ro = (const float*)d_in[5];
    const float* b_ro = (const float*)d_in[6];

    const int B = in_sizes[0] / (NOSC * DDIM);
    float* out = (float*)d_out;
    int write_x = (out_size >= B + B * NOSC * DDIM) ? 1 : 0;
    float* x_out = out + B;

    cudaFuncSetAttribute(akorn_kernel,
                         cudaFuncAttributeMaxDynamicSharedMemorySize, SM_TOTAL);

    wprep_kernel<<<256, 256>>>(W);
    hprep_kernel<<<32, 256>>>(h);
    akorn_kernel<<<B, 256, SM_TOTAL>>>(x, eta, A, w_ro, b_ro,
                                       out, x_out, write_x);
}

// round 17
// speedup vs baseline: 1.0627x; 1.0627x over previous
#include <cuda_runtime.h>
#include <cuda_fp16.h>
#include <math.h>

typedef unsigned int u32;

#define NOSC 256
#define DDIM 64
#define NSTEPS 10

// smem byte offsets (total ~74 KB -> 2 CTAs/SM)
#define SM_XHI 0
#define SM_XLO 32768
#define SM_OHI 65536
#define SM_RED 73728
#define SM_TOTAL 74752

// W prepacked fp16 (hi only) as ready-made m16n8k16 A-fragments:
// g_Wfrag[((p*8 + w)*2 + mt)*32 + lane] = {a0,a1,a2,a3} for that thread.
__device__ uint4 g_Wfrag[16 * 8 * 2 * 32];
// h prepacked fp16 pairs in fragment-lane-major order: [warp][seg*2+half][lane][uint4]
__device__ uint4 g_hpk[8 * 8 * 32];

__global__ void wprep_kernel(const float* __restrict__ W) {
    int idx = blockIdx.x * 256 + threadIdx.x;   // 32768 u32 slots
    int slot = idx & 3, lane = (idx >> 2) & 31;
    int mt = (idx >> 7) & 1, w = (idx >> 8) & 7, p = idx >> 11;
    int g = lane >> 2, tid4 = lane & 3;
    int i = w * 32 + mt * 16 + g + (slot & 1) * 8;        // W row
    int j = p * 16 + (slot >> 1) * 8 + tid4 * 2;          // W col (pair)
    __half h0 = __float2half_rn(W[i * 256 + j]);
    __half h1 = __float2half_rn(W[i * 256 + j + 1]);
    u32 val = (u32)__half_as_ushort(h0) | ((u32)__half_as_ushort(h1) << 16);
    ((u32*)g_Wfrag)[((((p * 8 + w) * 2 + mt) * 32) + lane) * 4 + slot] = val;
}

__global__ void hprep_kernel(const float* __restrict__ h) {
    int idx = blockIdx.x * 256 + threadIdx.x;   // 8192 = 256 rows x 32 col-pairs
    int i = idx >> 5, ep = idx & 31, e = ep * 2;
    float v0 = h[i * DDIM + e], v1 = h[i * DDIM + e + 1];
    __half h0 = __float2half_rn(v0), h1 = __float2half_rn(v1);
    u32 val = (u32)__half_as_ushort(h0) | ((u32)__half_as_ushort(h1) << 16);
    int w = i >> 5, mt = (i >> 4) & 1, hh = (i >> 3) & 1, g = i & 7;
    int nt = e >> 3, half = nt >> 2, slot = nt & 3, tid4 = (e >> 1) & 3;
    int lane = g * 4 + tid4, seg = mt * 2 + hh;
    ((u32*)g_hpk)[(((w * 8) + seg * 2 + half) * 32 + lane) * 4 + slot] = val;
}

// ---------------- PTX helpers (baseline sm_80-level; compile for plain sm_100) ----------------
__device__ __forceinline__ u32 smem_u32(const void* p) {
    u32 a; asm("{ .reg .u64 t; cvta.to.shared.u64 t, %1; cvt.u32.u64 %0, t; }"
               : "=r"(a) : "l"(p));
    return a;
}
__device__ __forceinline__ void ldsm_x4(u32 addr, u32* r) {
    asm volatile("ldmatrix.sync.aligned.m8n8.x4.shared.b16 {%0,%1,%2,%3}, [%4];"
                 : "=r"(r[0]), "=r"(r[1]), "=r"(r[2]), "=r"(r[3]) : "r"(addr));
}
__device__ __forceinline__ void ldsm_x4t(u32 addr, u32* r) {
    asm volatile("ldmatrix.sync.aligned.m8n8.x4.trans.shared.b16 {%0,%1,%2,%3}, [%4];"
                 : "=r"(r[0]), "=r"(r[1]), "=r"(r[2]), "=r"(r[3]) : "r"(addr));
}
__device__ __forceinline__ void mma16816(float* c, const u32* a, u32 b0, u32 b1) {
    asm volatile("mma.sync.aligned.m16n8k16.row.col.f32.f16.f16.f32 "
                 "{%0,%1,%2,%3}, {%4,%5,%6,%7}, {%8,%9}, {%0,%1,%2,%3};"
                 : "+f"(c[0]), "+f"(c[1]), "+f"(c[2]), "+f"(c[3])
                 : "r"(a[0]), "r"(a[1]), "r"(a[2]), "r"(a[3]), "r"(b0), "r"(b1));
}

__device__ __forceinline__ u32 pack_h2(float v0, float v1, u32& lo_out) {
    __half h0 = __float2half_rn(v0), h1 = __float2half_rn(v1);
    __half l0 = __float2half_rn(v0 - __half2float(h0));
    __half l1 = __float2half_rn(v1 - __half2float(h1));
    lo_out = (u32)__half_as_ushort(l0) | ((u32)__half_as_ushort(l1) << 16);
    return (u32)__half_as_ushort(h0) | ((u32)__half_as_ushort(h1) << 16);
}
__device__ __forceinline__ float h2f_lo(u32 v) {
    return __half2float(__ushort_as_half((unsigned short)(v & 0xffffu)));
}
__device__ __forceinline__ float h2f_hi(u32 v) {
    return __half2float(__ushort_as_half((unsigned short)(v >> 16)));
}

// XOR chunk swizzle: 128B rows, 16B granules; granule' = granule ^ (row & 7)
__device__ __forceinline__ u32 xaddr(int row, int chunk) {
    return (u32)(row * 128 + ((chunk ^ (row & 7)) << 4));
}

__global__ __launch_bounds__(256, 2)
void akorn_kernel(const float* __restrict__ x_in,
                  const float* __restrict__ eta_p,
                  const float* __restrict__ A,
                  const float* __restrict__ w_ro,
                  const float* __restrict__ b_ro,
                  float* __restrict__ out,
                  float* __restrict__ x_out,
                  int write_x)
{
    extern __shared__ char smp[];
    const int b = blockIdx.x;
    const int t = threadIdx.x;
    const int wid = t >> 5, lane = t & 31;
    const int g = lane >> 2, tid4 = lane & 3;
    const int lr = lane & 15, lh = lane >> 4;
    const int l8 = lane & 7, q8 = lane >> 3;
    const int wbase = wid * 32;
    const u32 sb = smem_u32(smp);
    const float eta = __ldg(eta_p);

    // W fragment base pointer for this warp/lane; pass stride = 512 uint4, mt stride = 32
    const uint4* wfp = g_Wfrag + (size_t)(wid * 2) * 32 + lane;

    // ---- initial x: load row t, normalize, store fp16 hi/lo (swizzled) ----
    {
        const float* xrow = x_in + (size_t)b * NOSC * DDIM + t * DDIM;
        float xr[DDIM]; float ss = 0.f;
        #pragma unroll
        for (int k = 0; k < 16; k++) {
            float4 v = __ldg((const float4*)&xrow[k * 4]);
            xr[4*k] = v.x; xr[4*k+1] = v.y; xr[4*k+2] = v.z; xr[4*k+3] = v.w;
            ss += v.x*v.x + v.y*v.y + v.z*v.z + v.w*v.w;
        }
        float inv = 1.0f / fmaxf(sqrtf(ss), 1e-12f);
        #pragma unroll
        for (int c = 0; c < DDIM; c++) xr[c] *= inv;
        #pragma unroll
        for (int q = 0; q < 8; q++) {
            u32 hs[4], ls[4];
            #pragma unroll
            for (int m = 0; m < 4; m++)
                hs[m] = pack_h2(xr[q*8 + 2*m], xr[q*8 + 2*m + 1], ls[m]);
            u32 a = xaddr(t, q);
            *(uint4*)(smp + SM_XHI + a) = make_uint4(hs[0], hs[1], hs[2], hs[3]);
            *(uint4*)(smp + SM_XLO + a) = make_uint4(ls[0], ls[1], ls[2], ls[3]);
        }
    }
    // ---- Omega = A - A^T, fp16 hi only (swizzled) ----
    if (t < DDIM) {
        int f = t;
        #pragma unroll 2
        for (int q = 0; q < 8; q++) {
            u32 hs[4];
            #pragma unroll
            for (int m = 0; m < 4; m++) {
                int e0 = q*8 + 2*m, e1 = e0 + 1;
                float v0 = __ldg(&A[f * DDIM + e0]) - __ldg(&A[e0 * DDIM + f]);
                float v1 = __ldg(&A[f * DDIM + e1]) - __ldg(&A[e1 * DDIM + f]);
                __half h0 = __float2half_rn(v0), h1 = __float2half_rn(v1);
                hs[m] = (u32)__half_as_ushort(h0) | ((u32)__half_as_ushort(h1) << 16);
            }
            *(uint4*)(smp + SM_OHI + xaddr(f, q)) = make_uint4(hs[0], hs[1], hs[2], hs[3]);
        }
    }
    __syncthreads();

    float part = 0.f;

    for (int step = 0; step < NSTEPS; step++) {
        float C[2][8][4];
        #pragma unroll
        for (int mt = 0; mt < 2; mt++)
            #pragma unroll
            for (int nt = 0; nt < 8; nt++)
                #pragma unroll
                for (int q = 0; q < 4; q++) C[mt][nt][q] = 0.f;

        // prefetch W fragments for pass 0 (covered by the Omega GEMM below)
        uint4 wa0 = __ldg(wfp);
        uint4 wa1 = __ldg(wfp + 32);

        // ---- Omega part: D += Xhi * Ohi  (A reads only OWN rows; B constant) ----
        #pragma unroll
        for (int ks = 0; ks < 4; ks++) {
            const int f0 = ks * 16;
            u32 ah[2][4];
            #pragma unroll
            for (int mt = 0; mt < 2; mt++) {
                int arow = wbase + mt*16 + lr;
                ldsm_x4(sb + SM_XHI + xaddr(arow, (f0 >> 3) + lh), ah[mt]);
            }
            #pragma unroll
            for (int nt2 = 0; nt2 < 8; nt2 += 2) {
                u32 bo[4];
                ldsm_x4t(sb + SM_OHI + xaddr(f0 + ((q8 & 1) << 3) + l8, nt2 + (q8 >> 1)), bo);
                #pragma unroll
                for (int mt = 0; mt < 2; mt++) {
                    mma16816(C[mt][nt2],     ah[mt], bo[0], bo[1]);
                    mma16816(C[mt][nt2 + 1], ah[mt], bo[2], bo[3]);
                }
            }
        }

        // ---- W part: 16 passes of 16 j-cols; A = register fragments (LDG, prefetch 1 ahead) ----
        for (int p = 0; p < 16; p++) {
            uint4 na0, na1;
            if (p < 15) {
                na0 = __ldg(wfp + (p + 1) * 512);
                na1 = __ldg(wfp + (p + 1) * 512 + 32);
            }
            const u32* aw0 = (const u32*)&wa0;
            const u32* aw1 = (const u32*)&wa1;
            const int jb = p * 16;
            #pragma unroll
            for (int nt2 = 0; nt2 < 8; nt2 += 2) {
                u32 bx[4];
                ldsm_x4t(sb + SM_XHI + xaddr(jb + ((q8 & 1) << 3) + l8, nt2 + (q8 >> 1)), bx);
                mma16816(C[0][nt2],     aw0, bx[0], bx[1]);
                mma16816(C[0][nt2 + 1], aw0, bx[2], bx[3]);
                mma16816(C[1][nt2],     aw1, bx[0], bx[1]);
                mma16816(C[1][nt2 + 1], aw1, bx[2], bx[3]);
            }
            wa0 = na0; wa1 = na1;
        }

        // ---- h fragments (global, read-only) ----
        uint4 hreg[8];
        {
            const uint4* hp = g_hpk + (size_t)(wid * 8) * 32 + lane;
            #pragma unroll
            for (int k = 0; k < 8; k++) hreg[k] = __ldg(hp + k * 32);
        }
        __syncthreads();   // all warps' LDSM reads of X done before epilogue rewrites X

        // ---- epilogue in fragment layout (fp32 state = hi + lo) ----
        #pragma unroll
        for (int mt = 0; mt < 2; mt++) {
            #pragma unroll
            for (int hh = 0; hh < 2; hh++) {
                const int row = wbase + mt*16 + g + hh*8;
                const int seg = mt * 2 + hh;
                float xv[16], dvv[16];
                float dot = 0.f;
                #pragma unroll
                for (int nt = 0; nt < 8; nt++) {
                    const u32* hw = (const u32*)&hreg[seg * 2 + (nt >> 2)];
                    u32 hv = hw[nt & 3];
                    float d0 = C[mt][nt][hh*2 + 0] + h2f_lo(hv);
                    float d1 = C[mt][nt][hh*2 + 1] + h2f_hi(hv);
                    u32 off = xaddr(row, nt) + (u32)(tid4 * 4);
                    u32 vh = *(const u32*)(smp + SM_XHI + off);
                    u32 vl = *(const u32*)(smp + SM_XLO + off);
                    float x0 = h2f_lo(vh) + h2f_lo(vl);
                    float x1 = h2f_hi(vh) + h2f_hi(vl);
                    dot += x0 * d0 + x1 * d1;
                    xv[nt*2] = x0; xv[nt*2+1] = x1;
                    dvv[nt*2] = d0; dvv[nt*2+1] = d1;
                }
                dot += __shfl_xor_sync(0xffffffffu, dot, 1);
                dot += __shfl_xor_sync(0xffffffffu, dot, 2);
                float ss = 0.f;
                #pragma unroll
                for (int c = 0; c < 16; c++) {
                    xv[c] = xv[c] + eta * (dvv[c] - dot * xv[c]);
                    ss += xv[c] * xv[c];
                }
                ss += __shfl_xor_sync(0xffffffffu, ss, 1);
                ss += __shfl_xor_sync(0xffffffffu, ss, 2);
                float inv = 1.0f / fmaxf(sqrtf(ss), 1e-12f);
                #pragma unroll
                for (int c = 0; c < 16; c++) xv[c] *= inv;
                #pragma unroll
                for (int nt = 0; nt < 8; nt++) {
                    u32 off = xaddr(row, nt) + (u32)(tid4 * 4);
                    u32 lo; u32 hi = pack_h2(xv[nt*2], xv[nt*2+1], lo);
                    *(u32*)(smp + SM_XHI + off) = hi;
                    *(u32*)(smp + SM_XLO + off) = lo;
                }
                if (step == NSTEPS - 1) {
                    #pragma unroll
                    for (int nt = 0; nt < 8; nt++) {
                        const int col = nt*8 + tid4*2;
                        float2 wv = *(const float2*)&w_ro[col];
                        part += xv[nt*2] * wv.x + xv[nt*2+1] * wv.y;
                    }
                    if (write_x) {
                        #pragma unroll
                        for (int nt = 0; nt < 8; nt++) {
                            const int col = nt*8 + tid4*2;
                            *(float2*)&x_out[(size_t)b * NOSC * DDIM + row * DDIM + col] =
                                make_float2(xv[nt*2], xv[nt*2+1]);
                        }
                    }
                }
            }
        }
        __syncthreads();   // new X visible before next step's LDSM
    }

    // ---- readout reduction ----
    float* red = (float*)(smp + SM_RED);
    red[t] = part;
    __syncthreads();
    #pragma unroll
    for (int s = 128; s > 0; s >>= 1) {
        if (t < s) red[t] += red[t + s];
        __syncthreads();
    }
    if (t == 0) out[b] = red[0] / (float)NOSC + __ldg(b_ro);
}

extern "C" void kernel_launch(void* const* d_in, const int* in_sizes, int n_in,
                              void* d_out, int out_size) {
    const float* x    = (const float*)d_in[0];
    const float* eta  = (const float*)d_in[1];
    const float* W    = (const float*)d_in[2];
    const float* A    = (const float*)d_in[3];
    const float* h    = (const float*)d_in[4];
    const float* w_ro = (const float*)d_in[5];
    const float* b_ro = (const float*)d_in[6];

    const int B = in_sizes[0] / (NOSC * DDIM);
    float* out = (float*)d_out;
    int write_x = (out_size >= B + B * NOSC * DDIM) ? 1 : 0;
    float* x_out = out + B;

    cudaFuncSetAttribute(akorn_kernel,
                         cudaFuncAttributeMaxDynamicSharedMemorySize, SM_TOTAL);

    wprep_kernel<<<128, 256>>>(W);
    hprep_kernel<<<32, 256>>>(h);
    akorn_kernel<<<B, 256, SM_TOTAL>>>(x, eta, A, w_ro, b_ro,
                                       out, x_out, write_x);
}